// round 11
// baseline (speedup 1.0000x reference)
#include <cuda_runtime.h>

// ---------------------------------------------------------------------------
// DNN_KalmanNet_SLAM — fused, latency-optimized, fully front-batched.
// 19 blocks x 256 threads; warp e owns GRU element e for both layers.
// ALL weights a warp needs are loaded in ONE burst at kernel entry
// (Whh0/Whh1/Wih1 scalar + Wih0 float4 -> ~60 LDG in flight), so L2/DRAM
// latency is paid once. Barrier 1 = full generation barrier; barrier 2 =
// arrive-and-exit (only head block waits). Counters self-reset each launch.
// ---------------------------------------------------------------------------

#define NB     19
#define NT     256
#define WPB    8
#define H1     560
#define GH     145
#define HEADB  (NB - 1)

__device__ float    g_h0[GH];
__device__ float    g_h1[GH];
__device__ unsigned g_cnt  = 0;
__device__ unsigned g_gen  = 0;
__device__ unsigned g_cnt2 = 0;

__device__ __forceinline__ float wsum(float v) {
#pragma unroll
    for (int o = 16; o; o >>= 1) v += __shfl_down_sync(0xffffffffu, v, o);
    return v;
}
__device__ __forceinline__ float sigm(float x) { return 1.0f / (1.0f + __expf(-x)); }
__device__ __forceinline__ float tanha(float x) {
    float y; asm("tanh.approx.f32 %0, %1;" : "=f"(y) : "f"(x)); return y;
}

__device__ __forceinline__ void gbar1() {
    __threadfence();
    __syncthreads();
    if (threadIdx.x == 0) {
        volatile unsigned* gp = &g_gen;
        unsigned my = *gp;
        if (atomicAdd(&g_cnt, 1u) == NB - 1u) {
            g_cnt = 0;
            __threadfence();
            atomicAdd(&g_gen, 1u);
        } else {
            while (*gp == my) { }
        }
    }
    __syncthreads();
    __threadfence();
}

__global__ __launch_bounds__(NT, 1)
void kalmannet_kernel(
    const float* __restrict__ state_inno, const float* __restrict__ obs_inno,
    const float* __restrict__ diff_state, const float* __restrict__ diff_obs,
    const float* __restrict__ W1,   const float* __restrict__ b1,
    const float* __restrict__ Wih0, const float* __restrict__ Whh0,
    const float* __restrict__ bih0, const float* __restrict__ bhh0,
    const float* __restrict__ Wih1, const float* __restrict__ Whh1,
    const float* __restrict__ bih1, const float* __restrict__ bhh1,
    const float* __restrict__ W2a,  const float* __restrict__ b2a,
    const float* __restrict__ W2b,  const float* __restrict__ b2b,
    const float* __restrict__ hn,
    float* __restrict__ out)
{
    __shared__ __align__(16) float s_l1[H1];
    __shared__ float s_x[16];
    __shared__ float s_hn[2 * GH];
    __shared__ float s_v[GH + 8];
    __shared__ float s_hid[40];
    __shared__ float s_w2a[40 * GH];    // head block only
    __shared__ float s_w2b[10 * 40];    // head block only
    __shared__ float s_b2a[40];
    __shared__ float s_b2b[10];

    const int t    = threadIdx.x;
    const int lane = t & 31;
    const int lw   = t >> 5;
    const int e    = blockIdx.x * WPB + lw;
    const bool act = (e < GH);

    // ================= FRONT-BATCHED WEIGHT LOADS (one burst) =============
    // Every weight this warp consumes later, issued NOW with max MLP.
    float  h0r[5], h0z[5], h0n[5];   // Whh0 rows (layer-0 recurrent)
    float  h1r[5], h1z[5], h1n[5];   // Whh1 rows (layer-1 recurrent)
    float  i1r[5], i1z[5], i1n[5];   // Wih1 rows (layer-1 input)
    float4 v0[5], v1[5], v2[5];      // Wih0 rows (layer-0 input), float4
    if (act) {
        const float* p0r = Whh0 + e * GH;
        const float* p0z = Whh0 + (e + GH) * GH;
        const float* p0n = Whh0 + (e + 2 * GH) * GH;
        const float* p1r = Whh1 + e * GH;
        const float* p1z = Whh1 + (e + GH) * GH;
        const float* p1n = Whh1 + (e + 2 * GH) * GH;
        const float* q1r = Wih1 + e * GH;
        const float* q1z = Wih1 + (e + GH) * GH;
        const float* q1n = Wih1 + (e + 2 * GH) * GH;
        const float4* u0 = (const float4*)(Wih0 + e * H1);
        const float4* u1 = (const float4*)(Wih0 + (e + GH) * H1);
        const float4* u2 = (const float4*)(Wih0 + (e + 2 * GH) * H1);
        const float4 z4 = make_float4(0.f, 0.f, 0.f, 0.f);
#pragma unroll
        for (int i = 0; i < 5; i++) {
            int k  = lane + 32 * i;
            bool g = (k < GH);
            bool g4 = (k < H1 / 4);
            h0r[i] = g ? __ldg(p0r + k) : 0.f;
            h0z[i] = g ? __ldg(p0z + k) : 0.f;
            h0n[i] = g ? __ldg(p0n + k) : 0.f;
            h1r[i] = g ? __ldg(p1r + k) : 0.f;
            h1z[i] = g ? __ldg(p1z + k) : 0.f;
            h1n[i] = g ? __ldg(p1n + k) : 0.f;
            i1r[i] = g ? __ldg(q1r + k) : 0.f;
            i1z[i] = g ? __ldg(q1z + k) : 0.f;
            i1n[i] = g ? __ldg(q1n + k) : 0.f;
            v0[i]  = g4 ? __ldg(u0 + k) : z4;
            v1[i]  = g4 ? __ldg(u1 + k) : z4;
            v2[i]  = g4 ? __ldg(u2 + k) : z4;
        }
    }

    // ---- inputs (overlap with weight loads in flight) ----
    if (t < 14) {
        float v;
        if      (t < 5)  v = state_inno[t];
        else if (t < 7)  v = obs_inno[t - 5];
        else if (t < 12) v = diff_state[t - 7];
        else             v = diff_obs[t - 12];
        s_x[t] = v;
    }
    for (int i = t; i < 2 * GH; i += NT) s_hn[i] = __ldg(hn + i);
    __syncthreads();

    // ---- l1 (redundant per block, cheap) ----
    for (int r = t; r < H1; r += NT) {
        const float* w = W1 + r * 14;
        float s = b1[r];
#pragma unroll
        for (int k = 0; k < 14; k++) s = fmaf(w[k], s_x[k], s);
        s_l1[r] = fmaxf(s, 0.0f);
    }

    // ---- head block: idle warps prefetch head weights into smem ----
    if (blockIdx.x == HEADB && lw >= 1) {
        for (int i = t - 32; i < 40 * GH; i += NT - 32) s_w2a[i] = W2a[i];
        if (lw == 1) {
            if (lane < 10) s_b2b[lane] = b2b[lane];
            for (int i = lane; i < 40; i += 32) s_b2a[i] = b2a[i];
        }
        if (lw >= 2) {
            for (int i = t - 64; i < 400; i += NT - 64) s_w2b[i] = W2b[i];
        }
    }

    // ---- recurrent dots (weights already in regs) ----
    float A0 = 0.f, A1 = 0.f, A2 = 0.f;
    float B0 = 0.f, B1 = 0.f, B2 = 0.f;
    float bi0r = 0.f, bi0z = 0.f, bi0n = 0.f;
    float bi1r = 0.f, bi1z = 0.f, bi1n = 0.f;
    if (act) {
#pragma unroll
        for (int i = 0; i < 5; i++) {
            int k = lane + 32 * i;
            float a = (k < GH) ? s_hn[k] : 0.f;
            float b = (k < GH) ? s_hn[GH + k] : 0.f;
            A0 = fmaf(h0r[i], a, A0);
            A1 = fmaf(h0z[i], a, A1);
            A2 = fmaf(h0n[i], a, A2);
            B0 = fmaf(h1r[i], b, B0);
            B1 = fmaf(h1z[i], b, B1);
            B2 = fmaf(h1n[i], b, B2);
        }
        A0 = wsum(A0); A1 = wsum(A1); A2 = wsum(A2);
        B0 = wsum(B0); B1 = wsum(B1); B2 = wsum(B2);
        if (lane == 0) {
            A0 += bhh0[e];  A1 += bhh0[e + GH];  A2 += bhh0[e + 2 * GH];
            B0 += bhh1[e];  B1 += bhh1[e + GH];  B2 += bhh1[e + 2 * GH];
            bi0r = bih0[e]; bi0z = bih0[e + GH]; bi0n = bih0[e + 2 * GH];
            bi1r = bih1[e]; bi1z = bih1[e + GH]; bi1n = bih1[e + 2 * GH];
        }
    }
    __syncthreads();   // s_l1 ready

    // ---- GRU layer 0: register Wih0 x smem l1 ----
    if (act) {
        const float4* xr = (const float4*)s_l1;
        float sr = 0.f, sz = 0.f, sn = 0.f;
#pragma unroll
        for (int i = 0; i < 5; i++) {
            int k = lane + 32 * i;
            if (k < H1 / 4) {
                float4 x = xr[k];
                sr += v0[i].x * x.x + v0[i].y * x.y + v0[i].z * x.z + v0[i].w * x.w;
                sz += v1[i].x * x.x + v1[i].y * x.y + v1[i].z * x.z + v1[i].w * x.w;
                sn += v2[i].x * x.x + v2[i].y * x.y + v2[i].z * x.z + v2[i].w * x.w;
            }
        }
        sr = wsum(sr); sz = wsum(sz); sn = wsum(sn);
        if (lane == 0) {
            float r = sigm(sr + bi0r + A0);
            float z = sigm(sz + bi0z + A1);
            float n = tanha(sn + bi0n + r * A2);
            g_h0[e] = (1.0f - z) * n + z * s_hn[e];
        }
    }

    gbar1();   // h0 visible

    // ---- GRU layer 1: register Wih1 x g_h0 (direct L2 read) ----
    if (act) {
        float sr = 0.f, sz = 0.f, sn = 0.f;
#pragma unroll
        for (int i = 0; i < 5; i++) {
            int k = lane + 32 * i;
            float x = (k < GH) ? g_h0[k] : 0.f;
            sr = fmaf(i1r[i], x, sr);
            sz = fmaf(i1z[i], x, sz);
            sn = fmaf(i1n[i], x, sn);
        }
        sr = wsum(sr); sz = wsum(sz); sn = wsum(sn);
        if (lane == 0) {
            float r = sigm(sr + bi1r + B0);
            float z = sigm(sz + bi1z + B1);
            float n = tanha(sn + bi1n + r * B2);
            g_h1[e] = (1.0f - z) * n + z * s_hn[GH + e];
        }
    }

    // ---- barrier 2: arrive-and-exit (only head block waits) ----
    __threadfence();
    __syncthreads();
    if (blockIdx.x != HEADB) {
        if (t == 0) atomicAdd(&g_cnt2, 1u);
        return;
    }
    if (t == 0) {
        volatile unsigned* c = &g_cnt2;
        while (*c != NB - 1u) { }
        g_cnt2 = 0;                 // reset for next graph replay
        __threadfence();
    }
    __syncthreads();
    __threadfence();

    // ---- output head (all weights already in smem) ----
    for (int i = t; i < GH; i += NT) s_v[i] = g_h1[i];
    __syncthreads();
    for (int r = lw; r < 40; r += WPB) {
        const float* w = &s_w2a[r * GH];
        float s = 0.f;
#pragma unroll 5
        for (int k = lane; k < GH; k += 32) s = fmaf(w[k], s_v[k], s);
        s = wsum(s);
        if (lane == 0) s_hid[r] = fmaxf(s + s_b2a[r], 0.0f);
    }
    __syncthreads();
    if (t < 10) {
        const float* w = &s_w2b[t * 40];
        float s = s_b2b[t];
#pragma unroll
        for (int k = 0; k < 40; k++) s = fmaf(w[k], s_hid[k], s);
        out[t] = s;
    }
}

extern "C" void kernel_launch(void* const* d_in, const int* in_sizes, int n_in,
                              void* d_out, int out_size) {
    (void)in_sizes; (void)n_in; (void)out_size;
    kalmannet_kernel<<<NB, NT>>>(
        (const float*)d_in[0],  (const float*)d_in[1],
        (const float*)d_in[2],  (const float*)d_in[3],
        (const float*)d_in[4],  (const float*)d_in[5],
        (const float*)d_in[6],  (const float*)d_in[7],
        (const float*)d_in[8],  (const float*)d_in[9],
        (const float*)d_in[10], (const float*)d_in[11],
        (const float*)d_in[12], (const float*)d_in[13],
        (const float*)d_in[14], (const float*)d_in[15],
        (const float*)d_in[16], (const float*)d_in[17],
        (const float*)d_in[18],
        (float*)d_out);
}

// round 13
// speedup vs baseline: 1.0252x; 1.0252x over previous
#include <cuda_runtime.h>

// ---------------------------------------------------------------------------
// DNN_KalmanNet_SLAM — fused, latency-optimized. Geometry: 10 x 512.
// Warp e owns GRU element e for both layers. Wih1 rows register-prefetched;
// head weights smem-prefetched by head block's idle warps; l1 recomputed
// redundantly per block. Barrier 1 = generation barrier over 10 blocks;
// barrier 2 = arrive-and-exit (only head block waits). Counters self-reset.
// ---------------------------------------------------------------------------

#define NB     10
#define NT     512
#define WPB    16
#define H1     560
#define GH     145
#define HEADB  (NB - 1)

__device__ float    g_h0[GH];
__device__ float    g_h1[GH];
__device__ unsigned g_cnt  = 0;
__device__ unsigned g_gen  = 0;
__device__ unsigned g_cnt2 = 0;

__device__ __forceinline__ float wsum(float v) {
#pragma unroll
    for (int o = 16; o; o >>= 1) v += __shfl_down_sync(0xffffffffu, v, o);
    return v;
}
__device__ __forceinline__ float sigm(float x) { return 1.0f / (1.0f + __expf(-x)); }
__device__ __forceinline__ float tanha(float x) {
    float y; asm("tanh.approx.f32 %0, %1;" : "=f"(y) : "f"(x)); return y;
}

__device__ __forceinline__ void gbar1() {
    __threadfence();
    __syncthreads();
    if (threadIdx.x == 0) {
        volatile unsigned* gp = &g_gen;
        unsigned my = *gp;
        if (atomicAdd(&g_cnt, 1u) == NB - 1u) {
            g_cnt = 0;
            __threadfence();
            atomicAdd(&g_gen, 1u);
        } else {
            while (*gp == my) { }
        }
    }
    __syncthreads();
    __threadfence();
}

__global__ __launch_bounds__(NT, 1)
void kalmannet_kernel(
    const float* __restrict__ state_inno, const float* __restrict__ obs_inno,
    const float* __restrict__ diff_state, const float* __restrict__ diff_obs,
    const float* __restrict__ W1,   const float* __restrict__ b1,
    const float* __restrict__ Wih0, const float* __restrict__ Whh0,
    const float* __restrict__ bih0, const float* __restrict__ bhh0,
    const float* __restrict__ Wih1, const float* __restrict__ Whh1,
    const float* __restrict__ bih1, const float* __restrict__ bhh1,
    const float* __restrict__ W2a,  const float* __restrict__ b2a,
    const float* __restrict__ W2b,  const float* __restrict__ b2b,
    const float* __restrict__ hn,
    float* __restrict__ out)
{
    __shared__ __align__(16) float s_l1[H1];
    __shared__ float s_x[16];
    __shared__ float s_hn[2 * GH];
    __shared__ float s_v[GH + 8];
    __shared__ float s_hid[40];
    __shared__ float s_w2a[40 * GH];    // head block only
    __shared__ float s_w2b[10 * 40];    // head block only
    __shared__ float s_b2a[40];
    __shared__ float s_b2b[10];

    const int t    = threadIdx.x;
    const int lane = t & 31;
    const int lw   = t >> 5;
    const int e    = blockIdx.x * WPB + lw;
    const bool act = (e < GH);

    // ---- inputs ----
    if (t < 14) {
        float v;
        if      (t < 5)  v = state_inno[t];
        else if (t < 7)  v = obs_inno[t - 5];
        else if (t < 12) v = diff_state[t - 7];
        else             v = diff_obs[t - 12];
        s_x[t] = v;
    }
    for (int i = t; i < 2 * GH; i += NT) s_hn[i] = __ldg(hn + i);
    __syncthreads();

    // ---- l1 (redundant per block, cheap) ----
    for (int r = t; r < H1; r += NT) {
        const float* w = W1 + r * 14;
        float s = b1[r];
#pragma unroll
        for (int k = 0; k < 14; k++) s = fmaf(w[k], s_x[k], s);
        s_l1[r] = fmaxf(s, 0.0f);
    }

    // ---- head block: idle warps prefetch ALL head weights into smem ----
    if (blockIdx.x == HEADB && lw >= 1) {
        for (int i = t - 32; i < 40 * GH; i += NT - 32) s_w2a[i] = W2a[i];
        if (lw == 1) {
            if (lane < 10) s_b2b[lane] = b2b[lane];
            for (int i = lane; i < 40; i += 32) s_b2a[i] = b2a[i];
        }
        if (lw >= 2) {
            for (int i = t - 64; i < 400; i += NT - 64) s_w2b[i] = W2b[i];
        }
    }

    // ---- prefetch Wih1 rows into registers (independent of h0) ----
    float w1r[5], w1z[5], w1n[5];
    if (act) {
        const float* pr = Wih1 + e * GH;
        const float* pz = Wih1 + (e + GH) * GH;
        const float* pn = Wih1 + (e + 2 * GH) * GH;
#pragma unroll
        for (int i = 0; i < 5; i++) {
            int k = lane + 32 * i;
            bool ok = (k < GH);
            w1r[i] = ok ? __ldg(pr + k) : 0.f;
            w1z[i] = ok ? __ldg(pz + k) : 0.f;
            w1n[i] = ok ? __ldg(pn + k) : 0.f;
        }
    }

    // ---- recurrent dots for BOTH layers (independent of l1/h0) ----
    float A0 = 0.f, A1 = 0.f, A2 = 0.f;
    float B0 = 0.f, B1 = 0.f, B2 = 0.f;
    float bi0r = 0.f, bi0z = 0.f, bi0n = 0.f;
    float bi1r = 0.f, bi1z = 0.f, bi1n = 0.f;
    if (act) {
        const float* q0r = Whh0 + e * GH;
        const float* q0z = Whh0 + (e + GH) * GH;
        const float* q0n = Whh0 + (e + 2 * GH) * GH;
        const float* q1r = Whh1 + e * GH;
        const float* q1z = Whh1 + (e + GH) * GH;
        const float* q1n = Whh1 + (e + 2 * GH) * GH;
#pragma unroll 5
        for (int k = lane; k < GH; k += 32) {
            float h0v = s_hn[k], h1v = s_hn[GH + k];
            A0 = fmaf(q0r[k], h0v, A0);
            A1 = fmaf(q0z[k], h0v, A1);
            A2 = fmaf(q0n[k], h0v, A2);
            B0 = fmaf(q1r[k], h1v, B0);
            B1 = fmaf(q1z[k], h1v, B1);
            B2 = fmaf(q1n[k], h1v, B2);
        }
        A0 = wsum(A0); A1 = wsum(A1); A2 = wsum(A2);
        B0 = wsum(B0); B1 = wsum(B1); B2 = wsum(B2);
        if (lane == 0) {
            A0 += bhh0[e];  A1 += bhh0[e + GH];  A2 += bhh0[e + 2 * GH];
            B0 += bhh1[e];  B1 += bhh1[e + GH];  B2 += bhh1[e + 2 * GH];
            bi0r = bih0[e]; bi0z = bih0[e + GH]; bi0n = bih0[e + 2 * GH];
            bi1r = bih1[e]; bi1z = bih1[e + GH]; bi1n = bih1[e + 2 * GH];
        }
    }
    __syncthreads();   // s_l1 ready

    // ---- GRU layer 0: Wih0 @ l1, float4 loads ----
    if (act) {
        const float4* xr = (const float4*)s_l1;
        const float4* wr = (const float4*)(Wih0 + e * H1);
        const float4* wz = (const float4*)(Wih0 + (e + GH) * H1);
        const float4* wn = (const float4*)(Wih0 + (e + 2 * GH) * H1);
        float sr = 0.f, sz = 0.f, sn = 0.f;
#pragma unroll
        for (int i = 0; i < 5; i++) {
            int k = lane + 32 * i;
            if (k < H1 / 4) {
                float4 x = xr[k];
                float4 a = wr[k];
                sr += a.x * x.x + a.y * x.y + a.z * x.z + a.w * x.w;
                float4 b = wz[k];
                sz += b.x * x.x + b.y * x.y + b.z * x.z + b.w * x.w;
                float4 c = wn[k];
                sn += c.x * x.x + c.y * x.y + c.z * x.z + c.w * x.w;
            }
        }
        sr = wsum(sr); sz = wsum(sz); sn = wsum(sn);
        if (lane == 0) {
            float r = sigm(sr + bi0r + A0);
            float z = sigm(sz + bi0z + A1);
            float n = tanha(sn + bi0n + r * A2);
            g_h0[e] = (1.0f - z) * n + z * s_hn[e];
        }
    }

    gbar1();   // h0 visible

    // ---- GRU layer 1: register Wih1 x g_h0 (direct L2 read) ----
    if (act) {
        float sr = 0.f, sz = 0.f, sn = 0.f;
#pragma unroll
        for (int i = 0; i < 5; i++) {
            int k = lane + 32 * i;
            float x = (k < GH) ? g_h0[k] : 0.f;
            sr = fmaf(w1r[i], x, sr);
            sz = fmaf(w1z[i], x, sz);
            sn = fmaf(w1n[i], x, sn);
        }
        sr = wsum(sr); sz = wsum(sz); sn = wsum(sn);
        if (lane == 0) {
            float r = sigm(sr + bi1r + B0);
            float z = sigm(sz + bi1z + B1);
            float n = tanha(sn + bi1n + r * B2);
            g_h1[e] = (1.0f - z) * n + z * s_hn[GH + e];
        }
    }

    // ---- barrier 2: arrive-and-exit (only head block waits) ----
    __threadfence();
    __syncthreads();
    if (blockIdx.x != HEADB) {
        if (t == 0) atomicAdd(&g_cnt2, 1u);
        return;
    }
    if (t == 0) {
        volatile unsigned* c = &g_cnt2;
        while (*c != NB - 1u) { }
        g_cnt2 = 0;                 // reset for next graph replay
        __threadfence();
    }
    __syncthreads();
    __threadfence();

    // ---- output head (all weights already in smem; 16 warps) ----
    for (int i = t; i < GH; i += NT) s_v[i] = g_h1[i];
    __syncthreads();
    for (int r = lw; r < 40; r += WPB) {
        const float* w = &s_w2a[r * GH];
        float s = 0.f;
#pragma unroll 5
        for (int k = lane; k < GH; k += 32) s = fmaf(w[k], s_v[k], s);
        s = wsum(s);
        if (lane == 0) s_hid[r] = fmaxf(s + s_b2a[r], 0.0f);
    }
    __syncthreads();
    if (t < 10) {
        const float* w = &s_w2b[t * 40];
        float s = s_b2b[t];
#pragma unroll
        for (int k = 0; k < 40; k++) s = fmaf(w[k], s_hid[k], s);
        out[t] = s;
    }
}

extern "C" void kernel_launch(void* const* d_in, const int* in_sizes, int n_in,
                              void* d_out, int out_size) {
    (void)in_sizes; (void)n_in; (void)out_size;
    kalmannet_kernel<<<NB, NT>>>(
        (const float*)d_in[0],  (const float*)d_in[1],
        (const float*)d_in[2],  (const float*)d_in[3],
        (const float*)d_in[4],  (const float*)d_in[5],
        (const float*)d_in[6],  (const float*)d_in[7],
        (const float*)d_in[8],  (const float*)d_in[9],
        (const float*)d_in[10], (const float*)d_in[11],
        (const float*)d_in[12], (const float*)d_in[13],
        (const float*)d_in[14], (const float*)d_in[15],
        (const float*)d_in[16], (const float*)d_in[17],
        (const float*)d_in[18],
        (float*)d_out);
}